// round 12
// baseline (speedup 1.0000x reference)
#include <cuda_runtime.h>
#include <cstdint>
#include <math.h>

#define NATOM 50000
#define AFEA  64
#define BFEA  41
#define FAN   169
#define CO    128
#define NROW  600000
#define TROWS 96          // rows per tile = 8 atoms exactly
#define NTT   6250        // NROW / 96
#define NT0   391         // ceil(NATOM/128)
#define KGB   296         // k1 grid (2 CTAs/SM)
#define XSTR  100         // xs row stride (96 + 4 pad)
#define WSTR  132         // ws row stride

// -------- scratch (device globals; allocation is forbidden) --------
__device__ float  g_PQ[NATOM * 256];          // [n][0:128]=P(self), [128:256]=Q(nbr)
__device__ float  g_sumed[NATOM * AFEA];
__device__ double g_p1s[KGB * CO],  g_p1q[KGB * CO];
__device__ double g_p2s[KGB * AFEA], g_p2q[KGB * AFEA];
__device__ float  g_scale1[CO], g_shift1[CO], g_scale2[AFEA], g_shift2[AFEA];

// -------- packed f32x2 helpers (sm_103a) --------
typedef unsigned long long ull_t;
#define FMA2(d, a, b, c) asm("fma.rn.f32x2 %0, %1, %2, %3;" : "=l"(d) : "l"(a), "l"(b), "l"(c))
__device__ __forceinline__ ull_t dupf(float x) {
    ull_t d; unsigned u = __float_as_uint(x);
    asm("mov.b64 %0, {%1, %2};" : "=l"(d) : "r"(u), "r"(u));
    return d;
}
__device__ __forceinline__ void unpk(float& lo, float& hi, ull_t v) {
    unsigned a, b;
    asm("mov.b64 {%0, %1}, %2;" : "=r"(a), "=r"(b) : "l"(v));
    lo = __uint_as_float(a); hi = __uint_as_float(b);
}
__device__ __forceinline__ float sigm(float x) { return __fdividef(1.0f, 1.0f + __expf(-x)); }
__device__ __forceinline__ float splus(float x) {
    return fmaxf(x, 0.0f) + __logf(1.0f + __expf(-fabsf(x)));
}

// Swizzled slot for weight column c in a k-row: conflict-free LDS.128 across 16 tc.
__device__ __forceinline__ int wsw(int c) {
    return (((c & 7) >> 2) << 6) + ((c >> 3) << 2) + (c & 3);
}

// -------- k0: per-atom projections P,Q (unchanged, 128x128 tiles, 8x8/thread) --------
__global__ __launch_bounds__(256, 2) void k0_proj(const float* __restrict__ atom,
                                                  const float* __restrict__ W) {
    __shared__ __align__(16) float ws[32 * WSTR];
    __shared__ __align__(16) float xs[32 * 136];
    const int tid = threadIdx.x;
    const int tc = tid & 15, tr = tid >> 4;
    const int r0 = blockIdx.x * 128;

    for (int h = 0; h < 2; ++h) {
        ull_t acc[8][4];
#pragma unroll
        for (int r = 0; r < 8; ++r)
#pragma unroll
            for (int c = 0; c < 4; ++c) acc[r][c] = 0ULL;

        for (int kc = 0; kc < 2; ++kc) {
            __syncthreads();
            for (int i = tid; i < 128 * 32; i += 256) {
                int row = i >> 5, kk = i & 31;
                int gr = r0 + row;
                xs[kk * 136 + row] = (gr < NATOM) ? atom[gr * AFEA + kc * 32 + kk] : 0.0f;
            }
            for (int i = tid; i < 128 * 32; i += 256) {
                int c = i >> 5, kk = i & 31;
                ws[kk * WSTR + wsw(c)] = W[c * FAN + h * 64 + kc * 32 + kk];
            }
            __syncthreads();
#pragma unroll 4
            for (int kk = 0; kk < 32; ++kk) {
                const float* xr = &xs[kk * 136 + tr * 8];
                const float* wr = &ws[kk * WSTR + tc * 4];
                float4 xa = *(const float4*)(xr);
                float4 xb = *(const float4*)(xr + 4);
                ulonglong2 wA = *(const ulonglong2*)(wr);
                ulonglong2 wB = *(const ulonglong2*)(wr + 64);
                float xr8[8] = {xa.x, xa.y, xa.z, xa.w, xb.x, xb.y, xb.z, xb.w};
#pragma unroll
                for (int r = 0; r < 8; ++r) {
                    ull_t xd = dupf(xr8[r]);
                    FMA2(acc[r][0], xd, wA.x, acc[r][0]);
                    FMA2(acc[r][1], xd, wA.y, acc[r][1]);
                    FMA2(acc[r][2], xd, wB.x, acc[r][2]);
                    FMA2(acc[r][3], xd, wB.y, acc[r][3]);
                }
            }
        }
#pragma unroll
        for (int r = 0; r < 8; ++r) {
            int g = r0 + tr * 8 + r;
            if (g < NATOM) {
                float v[8];
#pragma unroll
                for (int c = 0; c < 4; ++c) unpk(v[2 * c], v[2 * c + 1], acc[r][c]);
                float* dst = &g_PQ[(size_t)g * 256 + h * 128 + tc * 8];
                *(float4*)dst       = make_float4(v[0], v[1], v[2], v[3]);
                *(float4*)(dst + 4) = make_float4(v[4], v[5], v[6], v[7]);
            }
        }
    }
}

// -------- k1: edge GEMM, two passes sharing one body --------
// PASS2=false: gated -> BN1 partial sums (nothing stored).
// PASS2=true : gated -> BN1 affine -> sigm*splus -> atom sum -> g_sumed + BN2 partials.
template <bool PASS2>
__global__ __launch_bounds__(256, 2) void k1_pass(const float* __restrict__ nbr,
                                                  const int* __restrict__ idx,
                                                  const float* __restrict__ W,
                                                  const float* __restrict__ bvec) {
    __shared__ __align__(16) float ws[41 * WSTR];
    __shared__ __align__(16) float xs[41 * XSTR];
    __shared__ int sidx[TROWS];
    __shared__ double reds[128], redq[128];
    const int tid = threadIdx.x;
    const int tc = tid & 15, tr = tid >> 4;
    const int col0 = tc * 8;

    if (tid < 128) { reds[tid] = 0.0; redq[tid] = 0.0; }
    for (int i = tid; i < 41 * 128; i += 256) {   // edge weights once, swizzled
        int c = i / 41, kk = i - c * 41;
        ws[kk * WSTR + wsw(c)] = W[c * FAN + 128 + kk];
    }
    float bv[8];
    *(float4*)bv       = *(const float4*)&bvec[col0];
    *(float4*)(bv + 4) = *(const float4*)&bvec[col0 + 4];
    float sc1[8], sh1[8];
    if (PASS2) {
        *(float4*)sc1       = *(const float4*)&g_scale1[col0];
        *(float4*)(sc1 + 4) = *(const float4*)&g_scale1[col0 + 4];
        *(float4*)sh1       = *(const float4*)&g_shift1[col0];
        *(float4*)(sh1 + 4) = *(const float4*)&g_shift1[col0 + 4];
    }
    float fs[8], fq[8], asum[8];
#pragma unroll
    for (int c = 0; c < 8; ++c) { fs[c] = 0.0f; fq[c] = 0.0f; asum[c] = 0.0f; }

    for (int t = blockIdx.x; t < NTT; t += KGB) {
        const int r0 = t * TROWS;
        __syncthreads();
        for (int i = tid; i < TROWS * 41; i += 256) {
            int row = i / 41, kk = i - row * 41;
            xs[kk * XSTR + row] = nbr[(size_t)r0 * 41 + i];
        }
        if (tid < TROWS) sidx[tid] = idx[r0 + tid];
        __syncthreads();

        ull_t acc[6][4];
#pragma unroll
        for (int r = 0; r < 6; ++r)
#pragma unroll
            for (int c = 0; c < 4; ++c) acc[r][c] = 0ULL;
#pragma unroll 4
        for (int kk = 0; kk < 41; ++kk) {
            const float* xr = &xs[kk * XSTR + tr * 6];
            float2 xa = *(const float2*)(xr);
            float2 xb = *(const float2*)(xr + 2);
            float2 xc = *(const float2*)(xr + 4);
            const float* wr = &ws[kk * WSTR + tc * 4];
            ulonglong2 wA = *(const ulonglong2*)(wr);
            ulonglong2 wB = *(const ulonglong2*)(wr + 64);
            float xr6[6] = {xa.x, xa.y, xb.x, xb.y, xc.x, xc.y};
#pragma unroll
            for (int r = 0; r < 6; ++r) {
                ull_t xd = dupf(xr6[r]);
                FMA2(acc[r][0], xd, wA.x, acc[r][0]);
                FMA2(acc[r][1], xd, wA.y, acc[r][1]);
                FMA2(acc[r][2], xd, wB.x, acc[r][2]);
                FMA2(acc[r][3], xd, wB.y, acc[r][3]);
            }
        }

        // ---- epilogue ----
        const int atom = t * 8 + (tr >> 1);        // this thread's single atom
        float P8[8];
        {
            const float* Pp = &g_PQ[(size_t)atom * 256 + col0];
            *(float4*)P8       = *(const float4*)Pp;
            *(float4*)(P8 + 4) = *(const float4*)(Pp + 4);
        }
#pragma unroll
        for (int j = 0; j < 6; ++j) {
            float v[8];
#pragma unroll
            for (int c = 0; c < 4; ++c) unpk(v[2 * c], v[2 * c + 1], acc[j][c]);
            const float* Qp = &g_PQ[(size_t)sidx[tr * 6 + j] * 256 + 128 + col0];
            float4 q0 = *(const float4*)Qp;
            float4 q1 = *(const float4*)(Qp + 4);
            v[0] += P8[0] + q0.x + bv[0]; v[1] += P8[1] + q0.y + bv[1];
            v[2] += P8[2] + q0.z + bv[2]; v[3] += P8[3] + q0.w + bv[3];
            v[4] += P8[4] + q1.x + bv[4]; v[5] += P8[5] + q1.y + bv[5];
            v[6] += P8[6] + q1.z + bv[6]; v[7] += P8[7] + q1.w + bv[7];
            if (!PASS2) {
#pragma unroll
                for (int c = 0; c < 8; ++c) { fs[c] += v[c]; fq[c] += v[c] * v[c]; }
            } else {
#pragma unroll
                for (int c = 0; c < 8; ++c) {
                    float z = v[c] * sc1[c] + sh1[c];
                    float tv = (tc < 8) ? sigm(z) : splus(z);
                    float ov = __shfl_xor_sync(0xffffffffu, tv, 8);
                    if (tc < 8) asum[c] += tv * ov;
                }
            }
        }
        if (PASS2) {
            // merge the two half-atom row groups (tr even/odd are lanes l, l^16)
#pragma unroll
            for (int c = 0; c < 8; ++c)
                asum[c] += __shfl_xor_sync(0xffffffffu, asum[c], 16);
            if (tc < 8 && !(tr & 1)) {
                float* dst = &g_sumed[(size_t)atom * 64 + col0];
                *(float4*)dst       = make_float4(asum[0], asum[1], asum[2], asum[3]);
                *(float4*)(dst + 4) = make_float4(asum[4], asum[5], asum[6], asum[7]);
#pragma unroll
                for (int c = 0; c < 8; ++c) { fs[c] += asum[c]; fq[c] += asum[c] * asum[c]; }
            }
#pragma unroll
            for (int c = 0; c < 8; ++c) asum[c] = 0.0f;
        }
    }
    __syncthreads();
    if (!PASS2) {
#pragma unroll
        for (int c = 0; c < 8; ++c) {
            atomicAdd(&reds[col0 + c], (double)fs[c]);
            atomicAdd(&redq[col0 + c], (double)fq[c]);
        }
        __syncthreads();
        if (tid < 128) {
            g_p1s[blockIdx.x * CO + tid] = reds[tid];
            g_p1q[blockIdx.x * CO + tid] = redq[tid];
        }
    } else {
        if (tc < 8 && !(tr & 1)) {
#pragma unroll
            for (int c = 0; c < 8; ++c) {
                atomicAdd(&reds[col0 + c], (double)fs[c]);
                atomicAdd(&redq[col0 + c], (double)fq[c]);
            }
        }
        __syncthreads();
        if (tid < 64) {
            g_p2s[blockIdx.x * AFEA + tid] = reds[tid];
            g_p2q[blockIdx.x * AFEA + tid] = redq[tid];
        }
    }
}

// -------- k2: finalize BN1 (one block per channel) --------
__global__ void k2_fin(const float* __restrict__ g1, const float* __restrict__ b1) {
    __shared__ double sd[256], sq[256];
    const int ch = blockIdx.x, t = threadIdx.x;
    double s = 0.0, q = 0.0;
    for (int b = t; b < KGB; b += 256) { s += g_p1s[b * CO + ch]; q += g_p1q[b * CO + ch]; }
    sd[t] = s; sq[t] = q;
    __syncthreads();
    for (int o = 128; o > 0; o >>= 1) {
        if (t < o) { sd[t] += sd[t + o]; sq[t] += sq[t + o]; }
        __syncthreads();
    }
    if (t == 0) {
        double mean = sd[0] / (double)NROW;
        double var  = sq[0] / (double)NROW - mean * mean;
        float inv = (float)(1.0 / sqrt(var + 1e-5));
        float sc = g1[ch] * inv;
        g_scale1[ch] = sc;
        g_shift1[ch] = b1[ch] - (float)mean * sc;
    }
}

// -------- k4: finalize BN2 (one block per channel) --------
__global__ void k4_fin(const float* __restrict__ g2, const float* __restrict__ b2) {
    __shared__ double sd[256], sq[256];
    const int ch = blockIdx.x, t = threadIdx.x;
    double s = 0.0, q = 0.0;
    for (int b = t; b < KGB; b += 256) { s += g_p2s[b * AFEA + ch]; q += g_p2q[b * AFEA + ch]; }
    sd[t] = s; sq[t] = q;
    __syncthreads();
    for (int o = 128; o > 0; o >>= 1) {
        if (t < o) { sd[t] += sd[t + o]; sq[t] += sq[t + o]; }
        __syncthreads();
    }
    if (t == 0) {
        double mean = sd[0] / (double)NATOM;
        double var  = sq[0] / (double)NATOM - mean * mean;
        float inv = (float)(1.0 / sqrt(var + 1e-5));
        float sc = g2[ch] * inv;
        g_scale2[ch] = sc;
        g_shift2[ch] = b2[ch] - (float)mean * sc;
    }
}

// -------- k5: final softplus --------
__global__ void k5_out(const float* __restrict__ atom, float* __restrict__ out) {
    int i = blockIdx.x * blockDim.x + threadIdx.x;
    if (i < NATOM * AFEA) {
        int a = i & 63;
        float v = atom[i] + g_sumed[i] * g_scale2[a] + g_shift2[a];
        out[i] = splus(v);
    }
}

extern "C" void kernel_launch(void* const* d_in, const int* in_sizes, int n_in,
                              void* d_out, int out_size) {
    const float* atom = (const float*)d_in[0];
    const float* nbr  = (const float*)d_in[1];
    const int*   idx  = (const int*)d_in[2];
    const float* W    = (const float*)d_in[3];
    const float* bvec = (const float*)d_in[4];
    const float* bn1g = (const float*)d_in[5];
    const float* bn1b = (const float*)d_in[6];
    const float* bn2g = (const float*)d_in[7];
    const float* bn2b = (const float*)d_in[8];
    float* out = (float*)d_out;
    (void)in_sizes; (void)n_in; (void)out_size;

    k0_proj<<<NT0, 256>>>(atom, W);
    k1_pass<false><<<KGB, 256>>>(nbr, idx, W, bvec);   // BN1 stats
    k2_fin<<<CO, 256>>>(bn1g, bn1b);
    k1_pass<true><<<KGB, 256>>>(nbr, idx, W, bvec);    // recompute + act + atom sum
    k4_fin<<<AFEA, 256>>>(bn2g, bn2b);
    k5_out<<<(NATOM * AFEA + 255) / 256, 256>>>(atom, out);
}